// round 5
// baseline (speedup 1.0000x reference)
#include <cuda_runtime.h>

#define NEGV (-9e15f)

constexpr int N  = 512;
constexpr int F  = 64;
constexpr int BS = 8;
constexpr int WARPS = 8;
constexpr int THREADS = WARPS * 32;
constexpr int OUT_OFF = BS * N * F;   // 262144

__global__ __launch_bounds__(THREADS)
void gat_kernel(const float* __restrict__ x,    // [8,512,1]
                const int*   __restrict__ adj,  // [512,512]
                const float* __restrict__ ext,  // [8,512,8]
                const float* __restrict__ side, // [8,512,1]
                const float* __restrict__ W,    // [1,64]
                const float* __restrict__ a,    // [128,1]
                const float* __restrict__ WS,   // [1,64]
                const float* __restrict__ aS,   // [128,1]
                const float* __restrict__ WQ,   // [2,16]
                const float* __restrict__ WK,   // [2,16]
                const float* __restrict__ WV,   // [1,64]
                float* __restrict__ out)        // [2,8,512,64]
{
    __shared__ float s_c[8];                    // 8 scalar contractions
    __shared__ float s_u[N];                    // c2 * x_j
    __shared__ float s_v[N];                    // cs2 * side_j
    __shared__ float s_xs[N];                   // x_j
    __shared__ unsigned short s_j[WARPS][N];    // compacted active-j lists

    const int tid  = threadIdx.x;
    const int lane = tid & 31;
    const int w    = tid >> 5;
    const int row  = blockIdx.x * WARPS + w;    // b*512 + i  (whole CTA: same b)
    const int b    = row >> 9;
    const int i    = row & 511;

    // ---- prologue: warp w computes contraction w, broadcast via smem ----
    {
        float val;
        if (w < 4) {
            const float* Wp = (w < 2) ? W : WS;
            const float* ap = (w < 2) ? a : aS;
            const int off   = (w & 1) ? 64 : 0;
            val = Wp[lane] * ap[off + lane] + Wp[lane + 32] * ap[off + 32 + lane];
        } else {
            const int l16 = lane & 15;
            const float* q = WQ + (((w == 5) || (w == 7)) ? 16 : 0);
            const float* k = WK + ((w >= 6) ? 16 : 0);
            // 0.5 (16-wide dot duplicated across half-lanes) * 0.25 (1/sqrt(16))
            val = q[l16] * k[l16] * 0.125f;
        }
        #pragma unroll
        for (int o = 16; o; o >>= 1) val += __shfl_xor_sync(0xffffffffu, val, o);
        if (lane == 0) s_c[w] = val;
    }
    __syncthreads();

    const float c1 = s_c[0], c2 = s_c[1], cs1 = s_c[2], cs2 = s_c[3];
    const float A0 = s_c[4], B0 = s_c[5], A1  = s_c[6], B1  = s_c[7];

    const float* xb   = x    + (b << 9);
    const float* sb   = side + (b << 9);
    const float* extb = ext  + ((size_t)(b << 9) * 8);
    const int*   ar   = adj  + (i << 9);

    // ---- CTA-cooperative staging: x_j, u_j=c2*x_j, v_j=cs2*side_j ----
    #pragma unroll
    for (int idx = tid; idx < N; idx += THREADS) {
        float xj = xb[idx];
        float sj = sb[idx];
        s_xs[idx] = xj;
        s_u[idx]  = c2  * xj;
        s_v[idx]  = cs2 * sj;
    }
    __syncthreads();

    const float xi = s_xs[i];
    const float si = sb[i];
    const float t1 = xi * c1;
    const float t2 = si * cs1;
    const float xiA0 = xi * A0;
    const float xiA1 = xi * A1;

    float ei[8];
    {
        const float4* e4 = (const float4*)(extb + (size_t)i * 8);
        float4 ea = e4[0], eb = e4[1];
        ei[0]=ea.x; ei[1]=ea.y; ei[2]=ea.z; ei[3]=ea.w;
        ei[4]=eb.x; ei[5]=eb.y; ei[6]=eb.z; ei[7]=eb.w;
    }
    const float mean_ei = (ei[0]+ei[1]+ei[2]+ei[3]+ei[4]+ei[5]+ei[6]+ei[7]) * 0.125f;

    // ---- Pass A: logits, row max, warp-ballot compaction (no logit store) ----
    float lmax = NEGV;
    int   cnt  = 0;
    #pragma unroll
    for (int jj = 0; jj < N / 32; jj++) {
        int   j  = jj * 32 + lane;
        float e  = t1 + s_u[j];  e  = fmaxf(e,  0.2f * e);   // leakyrelu
        float es = t2 + s_v[j];  es = fmaxf(es, 0.2f * es);
        float s  = e + es;
        bool act = (ar[j] > 0) && (s > 0.f);
        unsigned mk = __ballot_sync(0xffffffffu, act);
        if (act) {
            int pos = cnt + __popc(mk & ((1u << lane) - 1u));
            s_j[w][pos] = (unsigned short)j;
            lmax = fmaxf(lmax, s);
        }
        cnt += __popc(mk);
    }
    #pragma unroll
    for (int o = 16; o; o >>= 1)
        lmax = fmaxf(lmax, __shfl_xor_sync(0xffffffffu, lmax, o));
    const float m = lmax;

    // Degenerate row (no active j): reference softmax is uniform over ALL j
    // (m = NEG, every p = exp(NEG-NEG) = 1). Emulate with p=1 over all 512 j.
    const bool degen = (cnt == 0);
    if (degen) {
        #pragma unroll
        for (int jj = 0; jj < N / 32; jj++)
            s_j[w][jj * 32 + lane] = (unsigned short)(jj * 32 + lane);
        cnt = N;
    }

    // ---- Pass B: dense over compacted active j ----
    float den = 0.f, ynum = 0.f, znum = 0.f;
    for (int t = lane; t < cnt; t += 32) {
        int   j  = s_j[w][t];
        float e  = t1 + s_u[j];  e  = fmaxf(e,  0.2f * e);
        float es = t2 + s_v[j];  es = fmaxf(es, 0.2f * es);
        float p  = degen ? 1.f : __expf(e + es - m);
        float xj = s_xs[j];
        den  += p;
        ynum += p * xj;
        float qk0 = fmaf(xj, B0, xiA0);
        float qk1 = fmaf(xj, B1, xiA1);
        const float4* f4 = (const float4*)(extb + (size_t)j * 8);
        float4 fa = f4[0], fb = f4[1];
        float ej[8] = {fa.x, fa.y, fa.z, fa.w, fb.x, fb.y, fb.z, fb.w};
        float s8 = 0.f, wn = 0.f;
        #pragma unroll
        for (int f = 0; f < 8; f++) {
            float df = fmaf(ei[f], qk0, ej[f] * qk1);
            // active df's are positive & bounded -> exp fp32-safe w/o max-sub
            float pf = (df > 0.f) ? __expf(df) : 0.f;
            s8 += pf;
            wn  = fmaf(pf, ei[f], wn);
        }
        // all-nonpositive inner row -> reference softmax uniform -> mean(ei)
        znum += p * ((s8 > 0.f) ? __fdividef(wn, s8) : mean_ei);
    }
    #pragma unroll
    for (int o = 16; o; o >>= 1) {
        den  += __shfl_xor_sync(0xffffffffu, den,  o);
        ynum += __shfl_xor_sync(0xffffffffu, ynum, o);
        znum += __shfl_xor_sync(0xffffffffu, znum, o);
    }
    const float y = ynum / den;
    const float z = znum / den;

    // ---- outputs: elu(y*W[f]), elu(z*WV[f]) ----
    size_t base = (size_t)row * F + lane;
    float v;
    v = y * W[lane];        out[base]                = (v > 0.f) ? v : expm1f(v);
    v = y * W[lane + 32];   out[base + 32]           = (v > 0.f) ? v : expm1f(v);
    v = z * WV[lane];       out[OUT_OFF + base]      = (v > 0.f) ? v : expm1f(v);
    v = z * WV[lane + 32];  out[OUT_OFF + base + 32] = (v > 0.f) ? v : expm1f(v);
}

extern "C" void kernel_launch(void* const* d_in, const int* in_sizes, int n_in,
                              void* d_out, int out_size) {
    const float* input = (const float*)d_in[0];
    const int*   adj   = (const int*)  d_in[1];
    const float* ext   = (const float*)d_in[2];
    const float* side  = (const float*)d_in[3];
    const float* W     = (const float*)d_in[4];
    const float* a     = (const float*)d_in[5];
    const float* WS    = (const float*)d_in[6];
    const float* aS    = (const float*)d_in[7];
    const float* WQ    = (const float*)d_in[8];
    const float* WK    = (const float*)d_in[9];
    const float* WV    = (const float*)d_in[10];
    float* out = (float*)d_out;

    gat_kernel<<<(BS * N) / WARPS, THREADS>>>(input, adj, ext, side,
                                              W, a, WS, aS, WQ, WK, WV, out);
}

// round 6
// speedup vs baseline: 1.0118x; 1.0118x over previous
#include <cuda_runtime.h>

#define NEGV (-9e15f)

constexpr int N  = 512;
constexpr int F  = 64;
constexpr int BS = 8;
constexpr int PAIRS   = 4;            // rows per CTA (2 warps each)
constexpr int THREADS = 256;          // 8 warps
constexpr int HALF    = N / 2;        // 256 j's per warp
constexpr int OUT_OFF = BS * N * F;   // 262144

__global__ __launch_bounds__(THREADS)
void gat_kernel(const float* __restrict__ x,    // [8,512,1]
                const int*   __restrict__ adj,  // [512,512]
                const float* __restrict__ ext,  // [8,512,8]
                const float* __restrict__ side, // [8,512,1]
                const float* __restrict__ W,    // [1,64]
                const float* __restrict__ a,    // [128,1]
                const float* __restrict__ WS,   // [1,64]
                const float* __restrict__ aS,   // [128,1]
                const float* __restrict__ WQ,   // [2,16]
                const float* __restrict__ WK,   // [2,16]
                const float* __restrict__ WV,   // [1,64]
                float* __restrict__ out)        // [2,8,512,64]
{
    __shared__ float s_c[8];                        // scalar contractions
    __shared__ float s_xs[N];                       // x_j   (batch-shared)
    __shared__ float s_sd[N];                       // side_j
    __shared__ unsigned short s_j [PAIRS][2][HALF]; // compacted j per half-warp
    __shared__ float          s_sc[PAIRS][2][HALF]; // compacted logit s
    __shared__ int   s_cnt [PAIRS][2];
    __shared__ float s_max [PAIRS][2];
    __shared__ float s_part[PAIRS][2][3];           // den / ynum / znum partials

    const int tid  = threadIdx.x;
    const int lane = tid & 31;
    const int w    = tid >> 5;
    const int pair = w >> 1;          // 0..3  -> row within CTA
    const int h    = w & 1;           // which half of j-range
    const int row  = blockIdx.x * PAIRS + pair;   // b*512 + i
    const int b    = row >> 9;
    const int i    = row & 511;

    // ---- prologue: warp w computes contraction w ----
    {
        float val;
        if (w < 4) {
            const float* Wp = (w < 2) ? W : WS;
            const float* ap = (w < 2) ? a : aS;
            const int off   = (w & 1) ? 64 : 0;
            val = Wp[lane] * ap[off + lane] + Wp[lane + 32] * ap[off + 32 + lane];
        } else {
            const int l16 = lane & 15;
            const float* q = WQ + (((w == 5) || (w == 7)) ? 16 : 0);
            const float* k = WK + ((w >= 6) ? 16 : 0);
            // 0.5 (16-wide dot duplicated across half-lanes) * 0.25 (1/sqrt(16))
            val = q[l16] * k[l16] * 0.125f;
        }
        #pragma unroll
        for (int o = 16; o; o >>= 1) val += __shfl_xor_sync(0xffffffffu, val, o);
        if (lane == 0) s_c[w] = val;
    }

    // ---- CTA-cooperative staging of raw x_j / side_j (no dependency on s_c) ----
    const float* xb   = x    + (b << 9);
    const float* sb   = side + (b << 9);
    const float* extb = ext  + ((size_t)(b << 9) * 8);
    #pragma unroll
    for (int idx = tid; idx < N; idx += THREADS) {
        s_xs[idx] = xb[idx];
        s_sd[idx] = sb[idx];
    }
    __syncthreads();   // #1

    const float c1 = s_c[0], c2 = s_c[1], cs1 = s_c[2], cs2 = s_c[3];
    const float A0 = s_c[4], B0 = s_c[5], A1  = s_c[6], B1  = s_c[7];

    const float xi = s_xs[i];
    const float si = s_sd[i];
    const float t1 = xi * c1;
    const float t2 = si * cs1;
    const float xiA0 = xi * A0;
    const float xiA1 = xi * A1;

    float ei[8];
    {
        const float4* e4 = (const float4*)(extb + (size_t)i * 8);
        float4 ea = e4[0], eb = e4[1];
        ei[0]=ea.x; ei[1]=ea.y; ei[2]=ea.z; ei[3]=ea.w;
        ei[4]=eb.x; ei[5]=eb.y; ei[6]=eb.z; ei[7]=eb.w;
    }
    const float mean_ei = (ei[0]+ei[1]+ei[2]+ei[3]+ei[4]+ei[5]+ei[6]+ei[7]) * 0.125f;

    const int* ar = adj + (i << 9);
    const int jbase = h * HALF;

    // ---- Pass A: this warp's 256 j's -> logits, max, ballot compaction ----
    float lmax = NEGV;
    int   cnt  = 0;
    #pragma unroll
    for (int jj = 0; jj < HALF / 32; jj++) {
        int   j  = jbase + jj * 32 + lane;
        float e  = fmaf(c2,  s_xs[j], t1);  e  = fmaxf(e,  0.2f * e);  // leakyrelu
        float es = fmaf(cs2, s_sd[j], t2);  es = fmaxf(es, 0.2f * es);
        float s  = e + es;
        bool act = (ar[j] > 0) && (s > 0.f);
        unsigned mk = __ballot_sync(0xffffffffu, act);
        if (act) {
            int pos = cnt + __popc(mk & ((1u << lane) - 1u));
            s_j [pair][h][pos] = (unsigned short)j;
            s_sc[pair][h][pos] = s;
            lmax = fmaxf(lmax, s);
        }
        cnt += __popc(mk);
    }
    #pragma unroll
    for (int o = 16; o; o >>= 1)
        lmax = fmaxf(lmax, __shfl_xor_sync(0xffffffffu, lmax, o));
    if (lane == 0) { s_max[pair][h] = lmax; s_cnt[pair][h] = cnt; }
    __syncthreads();   // #2

    const float m  = fmaxf(s_max[pair][0], s_max[pair][1]);
    const int total = s_cnt[pair][0] + s_cnt[pair][1];
    int mycnt = cnt;

    // Degenerate row (no active j anywhere): reference softmax is uniform over
    // ALL 512 j (m=NEG, every p=exp(NEG-NEG)=1). Each warp covers its half, p=1.
    const bool degen = (total == 0);
    if (degen) {
        #pragma unroll
        for (int jj = 0; jj < HALF / 32; jj++)
            s_j[pair][h][jj * 32 + lane] = (unsigned short)(jbase + jj * 32 + lane);
        mycnt = HALF;
    }

    // ---- Pass B: dense walk over own compacted segment ----
    float den = 0.f, ynum = 0.f, znum = 0.f;
    const unsigned short* jl = s_j [pair][h];
    const float*          sl = s_sc[pair][h];
    for (int t = lane; t < mycnt; t += 32) {
        int   j  = jl[t];
        float p  = degen ? 1.f : __expf(sl[t] - m);
        float xj = s_xs[j];
        den  += p;
        ynum += p * xj;
        float qk0 = fmaf(xj, B0, xiA0);
        float qk1 = fmaf(xj, B1, xiA1);
        const float4* f4 = (const float4*)(extb + (size_t)j * 8);
        float4 fa = f4[0], fb = f4[1];
        float ej[8] = {fa.x, fa.y, fa.z, fa.w, fb.x, fb.y, fb.z, fb.w};
        float s8 = 0.f, wn = 0.f;
        #pragma unroll
        for (int f = 0; f < 8; f++) {
            float df = fmaf(ei[f], qk0, ej[f] * qk1);
            // active df's are positive & bounded -> exp fp32-safe w/o max-sub
            float pf = (df > 0.f) ? __expf(df) : 0.f;
            s8 += pf;
            wn  = fmaf(pf, ei[f], wn);
        }
        // all-nonpositive inner row -> reference softmax uniform -> mean(ei)
        znum += p * ((s8 > 0.f) ? __fdividef(wn, s8) : mean_ei);
    }
    #pragma unroll
    for (int o = 16; o; o >>= 1) {
        den  += __shfl_xor_sync(0xffffffffu, den,  o);
        ynum += __shfl_xor_sync(0xffffffffu, ynum, o);
        znum += __shfl_xor_sync(0xffffffffu, znum, o);
    }
    if (lane == 0) {
        s_part[pair][h][0] = den;
        s_part[pair][h][1] = ynum;
        s_part[pair][h][2] = znum;
    }
    __syncthreads();   // #3

    const float D = s_part[pair][0][0] + s_part[pair][1][0];
    size_t base = (size_t)row * F + lane;
    float v;
    if (h == 0) {
        const float y = (s_part[pair][0][1] + s_part[pair][1][1]) / D;
        v = y * W[lane];       out[base]      = (v > 0.f) ? v : expm1f(v);
        v = y * W[lane + 32];  out[base + 32] = (v > 0.f) ? v : expm1f(v);
    } else {
        const float z = (s_part[pair][0][2] + s_part[pair][1][2]) / D;
        v = z * WV[lane];      out[OUT_OFF + base]      = (v > 0.f) ? v : expm1f(v);
        v = z * WV[lane + 32]; out[OUT_OFF + base + 32] = (v > 0.f) ? v : expm1f(v);
    }
}

extern "C" void kernel_launch(void* const* d_in, const int* in_sizes, int n_in,
                              void* d_out, int out_size) {
    const float* input = (const float*)d_in[0];
    const int*   adj   = (const int*)  d_in[1];
    const float* ext   = (const float*)d_in[2];
    const float* side  = (const float*)d_in[3];
    const float* W     = (const float*)d_in[4];
    const float* a     = (const float*)d_in[5];
    const float* WS    = (const float*)d_in[6];
    const float* aS    = (const float*)d_in[7];
    const float* WQ    = (const float*)d_in[8];
    const float* WK    = (const float*)d_in[9];
    const float* WV    = (const float*)d_in[10];
    float* out = (float*)d_out;

    gat_kernel<<<(BS * N) / PAIRS, THREADS>>>(input, adj, ext, side,
                                              W, a, WS, aS, WQ, WK, WV, out);
}